// round 11
// baseline (speedup 1.0000x reference)
#include <cuda_runtime.h>
#include <cuda_bf16.h>

#define NN 4096
#define MM 512
#define DD 32
#define NBLK 128        // 32 rows per block
#define NT   1024       // 32 warps; warp w owns m-columns [16w, 16w+16)

typedef unsigned long long ull;

// sm_103a packed fp32 FMA (FFMA2). Element 0 = low 32 bits.
__device__ __forceinline__ ull ffma2(ull a, ull b, ull c) {
    ull d;
    asm("fma.rn.f32x2 %0, %1, %2, %3;" : "=l"(d) : "l"(a), "l"(b), "l"(c));
    return d;
}
__device__ __forceinline__ float flo(ull v) { return __uint_as_float((unsigned)v); }
__device__ __forceinline__ float fhi(ull v) { return __uint_as_float((unsigned)(v >> 32)); }
__device__ __forceinline__ float sqrt_approx(float v) {
    float r;
    asm("sqrt.approx.f32 %0, %1;" : "=f"(r) : "f"(v));
    return r;
}
__device__ __forceinline__ float ex2_approx(float v) {
    float r;
    asm("ex2.approx.f32 %0, %1;" : "=f"(r) : "f"(v));
    return r;
}
__device__ __forceinline__ void cp_async16(unsigned dst, const void* src) {
    asm volatile("cp.async.cg.shared.global [%0], [%1], 16;" :: "r"(dst), "l"(src) : "memory");
}

// ---- smem layout (floats) --------------------------------------------------
#define RS_OFF   0                        // r [32][516] padded          16512
#define XS_OFF   16512                    // x [32][36] padded            1152
#define YSW_OFF  (XS_OFF + 1152)          // y warp slices [32][16][32]  16384
#define YN2W_OFF (YSW_OFF + 16384)        // |y|^2 per warp [32][16]       512
#define XN2_OFF  (YN2W_OFF + 512)         // |x|^2 [32]                     32
#define PART_OFF (XN2_OFF + 32)           // warp partials [3][32][32]    3072
#define SMEM_FLOATS (PART_OFF + 3072)
#define SMEM_BYTES  (SMEM_FLOATS * 4)     // ~147 KB

// ---------------------------------------------------------------------------
// Single fused kernel, 32 Sinkhorn rows per block. lane = row, warp = m-chunk.
//  r: cp.async.cg coalesced into padded smem; waited + block-synced only
//     between tile-0 dots and tile-0 epilogue (fully hidden).
//  y: WARP-LOCAL staging — each warp loads only its own 16-row chunk (2 KB,
//     coalesced), __syncwarp only. No block barrier on the 64 KB y stream.
//  x: block-staged (4 KB) — the only data under the launch barrier.
//  dots: d-packed f32x2 FFMAs, y via broadcast LDS.128 (1 wf/instr).
//  C = sqrt(|x|^2+|y|^2-2dot); K = ex2(-C*log2e/2); warp partials -> warp 0
//  scalar u-recurrence with block-local early stop; out[n] = u*T/(u+1e-8).
// ---------------------------------------------------------------------------
__global__ __launch_bounds__(NT) void sinkhorn_fused_kernel(
    const float* __restrict__ x,   // [NN, DD]
    const float* __restrict__ y,   // [MM, DD]
    const float* __restrict__ r,   // [NN, MM]
    float* __restrict__ out)       // [NN]
{
    extern __shared__ float sm[];
    float4* rs4  = (float4*)(sm + RS_OFF);    // [32][129] float4
    float4* xs4  = (float4*)(sm + XS_OFF);    // [32][9]  float4
    float4* ysw4 = (float4*)(sm + YSW_OFF);   // [32 warps][128] float4
    float*  yn2w = sm + YN2W_OFF;
    float*  xn2s = sm + XN2_OFF;
    float*  part = sm + PART_OFF;

    const int tid  = threadIdx.x;
    const int warp = tid >> 5;
    const int lane = tid & 31;
    const int nb   = blockIdx.x << 5;
    const int mc   = warp << 4;               // this warp's 16-column m-chunk

    // ---- r: cp.async.cg, coalesced (consecutive threads -> consecutive c4) -
    {
        const float4*  rg4 = (const float4*)r;
        const unsigned rs_base = (unsigned)__cvta_generic_to_shared(rs4);
#pragma unroll
        for (int k = 0; k < 4; k++) {
            int idx = tid + 1024 * k;
            int row = idx >> 7, c4 = idx & 127;
            cp_async16(rs_base + (unsigned)(row * 129 + c4) * 16u,
                       rg4 + (size_t)(nb + row) * 128 + c4);
        }
        asm volatile("cp.async.commit_group;" ::: "memory");
    }

    // ---- x staging (tid<256): padded copy + |x|^2 via 8-lane shfl ----------
    if (tid < 256) {
        int m = tid >> 3, slot = tid & 7;
        float4 a = ((const float4*)x)[(nb + m) * 8 + slot];
        xs4[m * 9 + slot] = a;
        float sq = fmaf(a.x, a.x, fmaf(a.y, a.y, fmaf(a.z, a.z, a.w * a.w)));
        sq += __shfl_xor_sync(0xffffffffu, sq, 1);
        sq += __shfl_xor_sync(0xffffffffu, sq, 2);
        sq += __shfl_xor_sync(0xffffffffu, sq, 4);
        if (slot == 0) xn2s[m] = sq;
    }
    __syncthreads();   // barrier 1: x, xn2 only (r in flight, y not started)

    // ---- y: WARP-LOCAL staging of this warp's 16 rows (2 KB, coalesced) ----
    {
        const float4* ygw = (const float4*)(y + (size_t)mc * DD);  // 128 f4
        float4*       dst = ysw4 + warp * 128;
#pragma unroll
        for (int k = 0; k < 4; k++) {
            int f = lane + 32 * k;
            float4 a = ygw[f];
            dst[f] = a;
            float sq = fmaf(a.x, a.x, fmaf(a.y, a.y, fmaf(a.z, a.z, a.w * a.w)));
            sq += __shfl_xor_sync(0xffffffffu, sq, 1);
            sq += __shfl_xor_sync(0xffffffffu, sq, 2);
            sq += __shfl_xor_sync(0xffffffffu, sq, 4);
            if ((lane & 7) == 0)
                yn2w[warp * 16 + (lane >> 3) + 4 * k] = sq;  // local row 0..15
        }
        __syncwarp();
    }

    // ---- main: 2 m-tiles of 8; r barrier hidden between tile0 dots/epi -----
    const ulonglong2* ys2 = (const ulonglong2*)(ysw4 + warp * 128); // [16][8]
    const ulonglong2* xs2 = (const ulonglong2*)xs4;                 // [32][9]
    const float xn2 = xn2s[lane];
    float Racc = 0.f, Sacc = 0.f, Tacc = 0.f;

#pragma unroll
    for (int mt = 0; mt < 2; mt++) {
        const int mbl = mt << 3;             // local m base within warp chunk
        ull A[8] = {0, 0, 0, 0, 0, 0, 0, 0};
#pragma unroll
        for (int p2 = 0; p2 < 8; p2++) {     // 4 d's per step
            ulonglong2 xp = xs2[lane * 9 + p2];            // own row's x quad
#pragma unroll
            for (int j = 0; j < 8; j++) {
                ulonglong2 yp = ys2[(mbl + j) * 8 + p2];   // broadcast LDS.128
                A[j] = ffma2(xp.x, yp.x, A[j]);
                A[j] = ffma2(xp.y, yp.y, A[j]);
            }
        }
        if (mt == 0) {                       // r landed during tile-0 dots
            asm volatile("cp.async.wait_group 0;" ::: "memory");
            __syncthreads();                 // barrier 2: all r tiles visible
        }

        float4 r4a = rs4[lane * 129 + (mc >> 2) + 2 * mt];
        float4 r4b = rs4[lane * 129 + (mc >> 2) + 2 * mt + 1];
        float rv[8] = { r4a.x, r4a.y, r4a.z, r4a.w, r4b.x, r4b.y, r4b.z, r4b.w };
#pragma unroll
        for (int j = 0; j < 8; j++) {
            float dot = flo(A[j]) + fhi(A[j]);
            float d2  = fmaf(-2.f, dot, xn2 + yn2w[warp * 16 + mbl + j]);
            float C   = sqrt_approx(fmaxf(d2, 0.f));
            float K   = ex2_approx(C * -0.72134752f);      // exp(-C/2)
            Racc += K;
            float Kr = K * rv[j];
            Sacc += Kr;
            Tacc = fmaf(Kr, C, Tacc);
        }
    }

    // ---- combine 32 warp partials in fixed order (deterministic) -----------
    part[(0 * 32 + warp) * 32 + lane] = Racc;
    part[(1 * 32 + warp) * 32 + lane] = Sacc;
    part[(2 * 32 + warp) * 32 + lane] = Tacc;
    __syncthreads();                         // barrier 3

    if (warp == 0) {
        float R = 0.f, S = 0.f, T = 0.f;
#pragma unroll
        for (int w = 0; w < 32; w++) {
            R += part[(0 * 32 + w) * 32 + lane];
            S += part[(1 * 32 + w) * 32 + lane];
            T += part[(2 * 32 + w) * 32 + lane];
        }

        // Scalar Sinkhorn recurrence, block-local early stop:
        //   iter 1:   u = 1/(R + 1e-8)
        //   iter t>1: u = 1/(S/(u+1e-8) + 1e-8)
        //   stop once mean_32 |u_new - u| < 0.1 (after applying update)
        float u = 1.f;
        bool done = false;
        for (int t = 0; t < 100 && !done; t++) {
            float denom = (t == 0) ? R : (S / (u + 1e-8f));
            float un = 1.f / (denom + 1e-8f);
            float e = fabsf(un - u);
            u = un;
#pragma unroll
            for (int off = 16; off > 0; off >>= 1)
                e += __shfl_xor_sync(0xffffffffu, e, off);
            done = (e < 0.1f * 32.f);        // uniform across warp
        }
        out[nb + lane] = u * T / (u + 1e-8f);
    }
}

extern "C" void kernel_launch(void* const* d_in, const int* in_sizes, int n_in,
                              void* d_out, int out_size)
{
    const float* x = (const float*)d_in[0];  // [4096, 32]
    const float* y = (const float*)d_in[1];  // [512, 32]
    const float* r = (const float*)d_in[2];  // [4096, 512]
    float* out = (float*)d_out;              // [4096]

    cudaFuncSetAttribute(sinkhorn_fused_kernel,
                         cudaFuncAttributeMaxDynamicSharedMemorySize, SMEM_BYTES);
    sinkhorn_fused_kernel<<<NBLK, NT, SMEM_BYTES>>>(x, y, r, out);
}